// round 4
// baseline (speedup 1.0000x reference)
#include <cuda_runtime.h>
#include <cstdint>

// ============================ problem constants ============================
#define N_   32
#define C_   256
#define H_   56
#define W_   56
#define PH_  58
#define PW_  58
#define PIX_ (H_*W_)                    // 3136
#define M_CNT_ (N_*PIX_)                // 100352 valid pixels
#define ROWS_ (N_*PH_*PW_)              // 107648 padded rows (= 841*128)
#define ROWS_PAD_ (ROWS_ + 128)         // tail so taps (+118) stay in-bounds
#define MTILES_ (ROWS_/128)             // 841

// ============================ device scratch ============================
__device__ __align__(16) signed char g_A1[(size_t)ROWS_PAD_*C_];   // 27.6 MB
__device__ __align__(16) signed char g_A2[(size_t)ROWS_PAD_*C_];
__device__ __align__(16) signed char g_Wt1[9*C_*C_];               // 0.59 MB
__device__ __align__(16) signed char g_Wt2[9*C_*C_];
__device__ __align__(16) short g_S1[(size_t)ROWS_*C_];             // 55.1 MB
__device__ __align__(16) short g_S2[(size_t)ROWS_*C_];
__device__ unsigned long long g_sum1[C_], g_sq1[C_], g_sum2[C_], g_sq2[C_];
__device__ float g_a1[C_], g_b1[C_], g_a2[C_], g_b2[C_];

// ============================ PTX helpers (base-target ISA only) ============================
__device__ __forceinline__ uint32_t smem_u32(const void* p) {
    uint32_t a;
    asm("{ .reg .u64 t; cvta.to.shared.u64 t, %1; cvt.u32.u64 %0, t; }" : "=r"(a) : "l"(p));
    return a;
}
__device__ __forceinline__ void cp16(uint32_t dst, const void* src) {
    asm volatile("cp.async.cg.shared.global [%0], [%1], 16;" :: "r"(dst), "l"(src));
}
__device__ __forceinline__ void cp_commit() {
    asm volatile("cp.async.commit_group;");
}
template <int N> __device__ __forceinline__ void cp_wait() {
    asm volatile("cp.async.wait_group %0;" :: "n"(N));
}
__device__ __forceinline__ void ldsm_x4(uint32_t* r, uint32_t addr) {
    asm volatile("ldmatrix.sync.aligned.m8n8.x4.shared.b16 {%0,%1,%2,%3}, [%4];"
                 : "=r"(r[0]), "=r"(r[1]), "=r"(r[2]), "=r"(r[3]) : "r"(addr));
}
__device__ __forceinline__ void imma16832(int* d, const uint32_t* a, uint32_t b0, uint32_t b1) {
    asm volatile("mma.sync.aligned.m16n8k32.row.col.s32.s8.s8.s32 "
                 "{%0,%1,%2,%3}, {%4,%5,%6,%7}, {%8,%9}, {%0,%1,%2,%3};"
                 : "+r"(d[0]), "+r"(d[1]), "+r"(d[2]), "+r"(d[3])
                 : "r"(a[0]), "r"(a[1]), "r"(a[2]), "r"(a[3]), "r"(b0), "r"(b1));
}

// ============================ small kernels ============================

// pack weights: w [O=256][I=256][3][3] float -> Wt[t][cout][cin] s8 (+1/-1)
__global__ void pack_w_k(const float* __restrict__ w, signed char* __restrict__ Wt) {
    int t = blockIdx.x;          // 0..8
    int c = threadIdx.x;         // cout
    int ky = t / 3, kx = t % 3;
    signed char* dst = Wt + ((size_t)t * C_ + c) * C_;
    for (int i0 = 0; i0 < C_; i0 += 16) {
        signed char buf[16];
        #pragma unroll
        for (int i = 0; i < 16; ++i) {
            float v = w[(((size_t)c * C_ + (i0 + i)) * 3 + ky) * 3 + kx];
            buf[i] = (v > 0.0f) ? 1 : -1;
        }
        *(uint4*)(dst + i0) = *(const uint4*)buf;
    }
}

__global__ void zero_stats_k() {
    int i = threadIdx.x;
    g_sum1[i] = 0ull; g_sq1[i] = 0ull; g_sum2[i] = 0ull; g_sq2[i] = 0ull;
}

// zero the +128 tail rows of both activation buffers
__global__ void zero_tail_k() {
    uint4 z = make_uint4(0, 0, 0, 0);
    size_t base = (size_t)ROWS_ * C_;
    for (int i = threadIdx.x; i < 128 * C_ / 16; i += blockDim.x) {
        *(uint4*)(g_A1 + base + (size_t)i * 16) = z;
        *(uint4*)(g_A2 + base + (size_t)i * 16) = z;
    }
}

// binarize x (NCHW f32) into padded s8 activation grid [row=(n,py,px)][c]
__global__ void pack_x_k(const float* __restrict__ x, signed char* __restrict__ A) {
    int px = threadIdx.x;        // 0..57
    int cg = threadIdx.y;        // 0..3 (64-ch groups)
    int py = blockIdx.x;         // 0..57
    int n  = blockIdx.y;
    size_t r = ((size_t)n * PH_ + py) * PW_ + px;
    signed char buf[64];
    if (px == 0 || px == PW_ - 1 || py == 0 || py == PH_ - 1) {
        #pragma unroll
        for (int i = 0; i < 64; ++i) buf[i] = 0;
    } else {
        const float* xp = x + (((size_t)n * C_ + cg * 64) * H_ + (py - 1)) * W_ + (px - 1);
        #pragma unroll
        for (int i = 0; i < 64; ++i)
            buf[i] = (xp[(size_t)i * PIX_] > 0.0f) ? 1 : -1;
    }
    uint4* dst = (uint4*)(A + r * C_ + cg * 64);
    const uint4* s = (const uint4*)buf;
    dst[0] = s[0]; dst[1] = s[1]; dst[2] = s[2]; dst[3] = s[3];
}

// ============================ IMMA GEMM-conv ============================
// CTA: 256 thr / 8 warps, tile 128M x 256N, K = 9 taps x 8 ksteps of 32.
#define STAGES    4
#define A_STRIDE  48
#define B_STRIDE  48
#define A_TILE_SM (128 * A_STRIDE)             // 6144
#define B_TILE_SM (256 * B_STRIDE)             // 12288
#define STAGE_SM  (A_TILE_SM + B_TILE_SM)      // 18432
#define SMEM_CONV (STAGES * STAGE_SM)          // 73728

__global__ __launch_bounds__(256, 1)
void conv_imma_k(const signed char* __restrict__ A,
                 const signed char* __restrict__ Wt,
                 short* __restrict__ S)
{
    extern __shared__ char smem[];
    const uint32_t sbase = smem_u32(smem);
    const int tid  = threadIdx.x;
    const int lane = tid & 31;
    const int wid  = tid >> 5;
    const int warpM = wid >> 2;       // 0..1
    const int warpN = wid & 3;        // 0..3
    const size_t rbase = (size_t)blockIdx.x * 128;

    int d[4][8][4];
    #pragma unroll
    for (int mf = 0; mf < 4; ++mf)
        #pragma unroll
        for (int nf = 0; nf < 8; ++nf)
            #pragma unroll
            for (int k = 0; k < 4; ++k) d[mf][nf][k] = 0;

    // per-thread cp.async chunk coordinates (fixed)
    const int a_row  = tid >> 1,  a_half = tid & 1;
    const int b_row0 = tid >> 1,  b_half0 = tid & 1;          // chunk tid
    const int b_row1 = (tid + 256) >> 1, b_half1 = tid & 1;   // chunk tid+256

    // issue one stage: i -> tap t = i>>3, kstep = i&7
    auto issue = [&](int i) {
        const int t = i >> 3, ks = i & 7;
        const int ky = (t >= 6) ? 2 : (t >= 3 ? 1 : 0);
        const int dt = 55 * ky + t;                 // {0,1,2,58,59,60,116,117,118}
        const uint32_t sm = sbase + (uint32_t)(i & (STAGES - 1)) * STAGE_SM;
        cp16(sm + a_row * A_STRIDE + a_half * 16,
             A + (rbase + dt + a_row) * C_ + ks * 32 + a_half * 16);
        const uint32_t bsm = sm + A_TILE_SM;
        cp16(bsm + b_row0 * B_STRIDE + b_half0 * 16,
             Wt + ((size_t)t * C_ + b_row0) * C_ + ks * 32 + b_half0 * 16);
        cp16(bsm + b_row1 * B_STRIDE + b_half1 * 16,
             Wt + ((size_t)t * C_ + b_row1) * C_ + ks * 32 + b_half1 * 16);
        cp_commit();
    };

    issue(0); issue(1); issue(2);

    // fragment-load smem offsets (fixed per thread)
    const uint32_t a_off = (uint32_t)((warpM * 64 + ((lane >> 3) & 1) * 8 + (lane & 7)) * A_STRIDE
                                      + (lane >> 4) * 16);
    const uint32_t b_off = (uint32_t)((warpN * 64 + ((lane >> 4) & 1) * 8 + (lane & 7)) * B_STRIDE
                                      + ((lane >> 3) & 1) * 16);

    for (int i = 0; i < 72; ++i) {
        const int rem = 71 - i;
        if (rem >= 2) cp_wait<2>(); else if (rem == 1) cp_wait<1>(); else cp_wait<0>();
        __syncthreads();
        if (i + 3 < 72) issue(i + 3);

        const uint32_t sm  = sbase + (uint32_t)(i & (STAGES - 1)) * STAGE_SM;
        const uint32_t bsm = sm + A_TILE_SM;

        uint32_t a[4][4], b[4][4];
        #pragma unroll
        for (int mf = 0; mf < 4; ++mf)
            ldsm_x4(a[mf], sm + a_off + (uint32_t)(mf * 16 * A_STRIDE));
        #pragma unroll
        for (int p = 0; p < 4; ++p)
            ldsm_x4(b[p], bsm + b_off + (uint32_t)(p * 16 * B_STRIDE));

        #pragma unroll
        for (int mf = 0; mf < 4; ++mf)
            #pragma unroll
            for (int nf = 0; nf < 8; ++nf)
                imma16832(d[mf][nf], a[mf], b[nf >> 1][(nf & 1) * 2], b[nf >> 1][(nf & 1) * 2 + 1]);
    }

    // epilogue: D frag rows = lane>>2 (+8), cols = 2*(lane&3)(+1); exact sums -> int16
    #pragma unroll
    for (int mf = 0; mf < 4; ++mf) {
        const size_t row0 = rbase + warpM * 64 + mf * 16 + (lane >> 2);
        #pragma unroll
        for (int nf = 0; nf < 8; ++nf) {
            const int col = warpN * 64 + nf * 8 + 2 * (lane & 3);
            short2 v0 = make_short2((short)d[mf][nf][0], (short)d[mf][nf][1]);
            short2 v1 = make_short2((short)d[mf][nf][2], (short)d[mf][nf][3]);
            *(short2*)(S + row0 * C_ + col)       = v0;
            *(short2*)(S + (row0 + 8) * C_ + col) = v1;
        }
    }
}

// ============================ stats / bn / thresh / final ============================

__global__ void stats_k(const short* __restrict__ S,
                        unsigned long long* __restrict__ sum,
                        unsigned long long* __restrict__ sq) {
    int oy = blockIdx.x, n = blockIdx.y, c = threadIdx.x;
    const short* base = S + (((size_t)n * (PH_ * PW_)) + (size_t)oy * PW_) * C_ + c;
    int s = 0, q = 0;
    for (int ox = 0; ox < 56; ++ox) {
        int v = base[(size_t)ox * C_];
        s += v; q += v * v;
    }
    atomicAdd(&sum[c], (unsigned long long)(long long)s);
    atomicAdd(&sq[c],  (unsigned long long)(long long)q);
}

__global__ void bnparams_k(const unsigned long long* __restrict__ sum,
                           const unsigned long long* __restrict__ sq,
                           const float* __restrict__ gamma, const float* __restrict__ beta,
                           float* __restrict__ a, float* __restrict__ b) {
    int c = threadIdx.x;
    const double M = (double)M_CNT_;
    double mS = (double)(long long)sum[c] / M;
    double vS = (double)(long long)sq[c] / M - mS * mS;
    double m = 0.5 * mS;            // y = 0.5 * S
    double v = 0.25 * vS;
    double r = 1.0 / sqrt(v + 1e-5);
    double g = (double)gamma[c];
    a[c] = (float)(0.5 * r * g);
    b[c] = (float)((double)beta[c] - m * r * g);
}

// threshold conv1 sums -> s8 padded activations for conv2
__global__ void thresh_pack_k(const short* __restrict__ S,
                              const float* __restrict__ a, const float* __restrict__ b,
                              signed char* __restrict__ A2) {
    int c = threadIdx.x;           // 0..255 (coalesced)
    int py = blockIdx.x, n = blockIdx.y;
    float av = a[c], bv = b[c];
    signed char* dst = A2 + (((size_t)n * PH_ + py) * PW_) * C_ + c;
    bool rowvalid = (py >= 1 && py <= 56);
    for (int px = 0; px < PW_; ++px) {
        signed char byte = 0;
        if (rowvalid && px >= 1 && px <= 56) {
            int v = S[(((size_t)n * (PH_ * PW_)) + (size_t)(py - 1) * PW_ + (px - 1)) * C_ + c];
            byte = (av * (float)v + bv > 0.0f) ? 1 : -1;
        }
        dst[(size_t)px * C_] = byte;
    }
}

// final: out = clip(a2*S2 + b2 + x, -1, 1) with smem transpose for coalescing
__global__ __launch_bounds__(256)
void final_k(const short* __restrict__ S2,
             const float* __restrict__ a, const float* __restrict__ b,
             const float* __restrict__ x, float* __restrict__ out) {
    __shared__ short tile[32][33];
    int n = blockIdx.z, pt = blockIdx.x, ct = blockIdx.y;
    int tx = threadIdx.x, ty = threadIdx.y;        // (32, 8)
    #pragma unroll
    for (int i = 0; i < 4; ++i) {
        int rl = ty + i * 8;
        int p = pt * 32 + rl;
        if (p < PH_ * PW_)
            tile[rl][tx] = S2[((size_t)n * (PH_ * PW_) + p) * C_ + ct * 32 + tx];
    }
    __syncthreads();
    int p = pt * 32 + tx;
    if (p < PH_ * PW_) {
        int py = p / PW_, px = p % PW_;
        if (py < 56 && px < 56) {
            #pragma unroll
            for (int i = 0; i < 4; ++i) {
                int cl = ty + i * 8;
                int c = ct * 32 + cl;
                size_t oi = (((size_t)n * C_ + c) * H_ + py) * W_ + px;
                float v = a[c] * (float)tile[tx][cl] + b[c] + x[oi];
                out[oi] = fminf(1.0f, fmaxf(-1.0f, v));
            }
        }
    }
}

// ============================ launch ============================
extern "C" void kernel_launch(void* const* d_in, const int* in_sizes, int n_in,
                              void* d_out, int out_size) {
    const float* x  = (const float*)d_in[0];
    const float* w1 = (const float*)d_in[1];
    const float* g1 = (const float*)d_in[2];
    const float* b1 = (const float*)d_in[3];
    const float* w2 = (const float*)d_in[4];
    const float* g2 = (const float*)d_in[5];
    const float* b2 = (const float*)d_in[6];
    float* out = (float*)d_out;

    void *pA1, *pA2, *pW1, *pW2, *pS1, *pS2;
    void *psum1, *psq1, *psum2, *psq2, *pa1, *pb1, *pa2, *pb2;
    cudaGetSymbolAddress(&pA1, g_A1);   cudaGetSymbolAddress(&pA2, g_A2);
    cudaGetSymbolAddress(&pW1, g_Wt1);  cudaGetSymbolAddress(&pW2, g_Wt2);
    cudaGetSymbolAddress(&pS1, g_S1);   cudaGetSymbolAddress(&pS2, g_S2);
    cudaGetSymbolAddress(&psum1, g_sum1); cudaGetSymbolAddress(&psq1, g_sq1);
    cudaGetSymbolAddress(&psum2, g_sum2); cudaGetSymbolAddress(&psq2, g_sq2);
    cudaGetSymbolAddress(&pa1, g_a1);   cudaGetSymbolAddress(&pb1, g_b1);
    cudaGetSymbolAddress(&pa2, g_a2);   cudaGetSymbolAddress(&pb2, g_b2);

    cudaFuncSetAttribute(conv_imma_k, cudaFuncAttributeMaxDynamicSharedMemorySize, SMEM_CONV);

    // launches 0..4 (so the profiled skip-5 launch is conv_imma_k)
    pack_w_k<<<9, 256>>>(w1, (signed char*)pW1);
    pack_w_k<<<9, 256>>>(w2, (signed char*)pW2);
    zero_stats_k<<<1, 256>>>();
    zero_tail_k<<<1, 256>>>();
    pack_x_k<<<dim3(PH_, N_), dim3(PW_, 4)>>>(x, (signed char*)pA1);

    // conv1 (launch 5)
    conv_imma_k<<<MTILES_, 256, SMEM_CONV>>>(
        (const signed char*)pA1, (const signed char*)pW1, (short*)pS1);

    stats_k<<<dim3(56, N_), 256>>>((const short*)pS1,
        (unsigned long long*)psum1, (unsigned long long*)psq1);
    bnparams_k<<<1, 256>>>((const unsigned long long*)psum1, (const unsigned long long*)psq1,
                           g1, b1, (float*)pa1, (float*)pb1);
    thresh_pack_k<<<dim3(PH_, N_), 256>>>((const short*)pS1,
        (const float*)pa1, (const float*)pb1, (signed char*)pA2);

    // conv2
    conv_imma_k<<<MTILES_, 256, SMEM_CONV>>>(
        (const signed char*)pA2, (const signed char*)pW2, (short*)pS2);

    stats_k<<<dim3(56, N_), 256>>>((const short*)pS2,
        (unsigned long long*)psum2, (unsigned long long*)psq2);
    bnparams_k<<<1, 256>>>((const unsigned long long*)psum2, (const unsigned long long*)psq2,
                           g2, b2, (float*)pa2, (float*)pb2);

    final_k<<<dim3((PH_ * PW_ + 31) / 32, 8, N_), dim3(32, 8)>>>(
        (const short*)pS2, (const float*)pa2, (const float*)pb2, x, out);
}

// round 5
// speedup vs baseline: 2.2530x; 2.2530x over previous
#include <cuda_runtime.h>
#include <cstdint>

typedef unsigned long long u64;
typedef unsigned long long ull;

// ============================ problem constants ============================
#define N_   32
#define C_   256
#define H_   56
#define W_   56
#define PH_  58
#define PW_  58
#define PIX_ (H_*W_)                 // 3136
#define M_CNT_ (N_*PIX_)             // 100352
#define NW_  4                       // u64 words per pixel (256 ch)

// ============================ device scratch ============================
__device__ __align__(16) u64 g_Xp1[(size_t)N_*PH_*PW_*NW_];   // packed padded input (3.44 MB)
__device__ __align__(16) u64 g_Xp2[(size_t)N_*PH_*PW_*NW_];   // packed padded act2
__device__ __align__(16) u64 g_Wp1[9*C_*NW_];
__device__ __align__(16) u64 g_Wp2[9*C_*NW_];
__device__ int  g_c1[9*C_];
__device__ int  g_c2[9*C_];
__device__ __align__(16) short g_S1[(size_t)M_CNT_*C_];       // [pixel][cout] (51.4 MB)
__device__ __align__(16) short g_S2[(size_t)M_CNT_*C_];
__device__ ull g_sum1[C_], g_sq1[C_], g_sum2[C_], g_sq2[C_];
__device__ float g_a1[C_], g_b1[C_], g_a2[C_], g_b2[C_];

// ============================ setup kernels ============================
__global__ void zero_stats_k() {
    int i = threadIdx.x;
    g_sum1[i] = 0ull; g_sq1[i] = 0ull; g_sum2[i] = 0ull; g_sq2[i] = 0ull;
}

// pack weights: w [O=256][I=256][3][3] f32 -> Wp[t][cout][4] u64 (bit=1 means +1)
__global__ void pack_w_k(const float* __restrict__ w, u64* __restrict__ Wp) {
    int t = blockIdx.x;          // 0..8
    int c = threadIdx.x;         // cout
    int ky = t / 3, kx = t % 3;
    #pragma unroll
    for (int j = 0; j < NW_; ++j) {
        u64 bits = 0ull;
        #pragma unroll 4
        for (int cl = 0; cl < 64; ++cl) {
            int cin = j * 64 + cl;
            float v = w[(((size_t)c * C_ + cin) * 3 + ky) * 3 + kx];
            bits |= (u64)(v > 0.0f) << cl;
        }
        Wp[((size_t)t * C_ + c) * NW_ + j] = bits;
    }
}

// border corrections: corr[type][c] = sum over invalid taps of (256 - 2*popc(w_tap))
__global__ void corr_w_k(const u64* __restrict__ Wp, int* __restrict__ corr) {
    int c = threadIdx.x;
    int pc[9];
    #pragma unroll
    for (int t = 0; t < 9; ++t) {
        int s = 0;
        #pragma unroll
        for (int j = 0; j < NW_; ++j) s += __popcll(Wp[((size_t)t * C_ + c) * NW_ + j]);
        pc[t] = s;
    }
    for (int type = 0; type < 9; ++type) {
        int rt = type / 3, ct = type % 3;
        int s = 0;
        #pragma unroll
        for (int ky = 0; ky < 3; ++ky)
            #pragma unroll
            for (int kx = 0; kx < 3; ++kx) {
                bool rinv = (rt == 0 && ky == 0) || (rt == 2 && ky == 2);
                bool cinv = (ct == 0 && kx == 0) || (ct == 2 && kx == 2);
                if (rinv || cinv) s += 256 - 2 * pc[ky * 3 + kx];
            }
        corr[type * C_ + c] = s;
    }
}

// binarize x (NCHW f32) -> padded packed bitplanes, halo = 0 bits
__global__ void pack_x_k(const float* __restrict__ x, u64* __restrict__ Xp) {
    int px = threadIdx.x;   // 0..57
    int j  = threadIdx.y;   // 0..3
    int py = blockIdx.x;    // 0..57
    int n  = blockIdx.y;
    size_t oidx = (((size_t)n * PH_ + py) * PW_ + px) * NW_ + j;
    if (px == 0 || px == PW_ - 1 || py == 0 || py == PH_ - 1) { Xp[oidx] = 0ull; return; }
    const float* xp = x + (((size_t)n * C_ + j * 64) * H_ + (py - 1)) * W_ + (px - 1);
    u64 bits = 0ull;
    #pragma unroll 8
    for (int cl = 0; cl < 64; ++cl)
        bits |= (u64)(xp[(size_t)cl * PIX_] > 0.0f) << cl;
    Xp[oidx] = bits;
}

// ============================ hot kernel: XNOR-popcount conv ============================
// thread = cout (weights in registers); x rows broadcast from smem; 2 pixels/iter.
__global__ __launch_bounds__(256, 2)
void conv_pop_k(const u64* __restrict__ Xp,
                const u64* __restrict__ Wp,
                const int* __restrict__ corr,
                short* __restrict__ S)
{
    __shared__ u64 sx[3 * PW_ * NW_];     // 696 u64 = 5568 B
    const int c  = threadIdx.x;
    const int oy = blockIdx.x;
    const int n  = blockIdx.y;

    // weights for this cout -> registers (72 regs)
    u64 w[9][4];
    #pragma unroll
    for (int t = 0; t < 9; ++t) {
        const ulonglong2* p = (const ulonglong2*)&Wp[((size_t)t * C_ + c) * NW_];
        ulonglong2 v0 = p[0], v1 = p[1];
        w[t][0] = v0.x; w[t][1] = v0.y; w[t][2] = v1.x; w[t][3] = v1.y;
    }
    const int rt = (oy == 0) ? 0 : ((oy == H_ - 1) ? 2 : 1);
    const int cL = corr[(rt * 3 + 0) * C_ + c];
    const int cM = corr[(rt * 3 + 1) * C_ + c];
    const int cR = corr[(rt * 3 + 2) * C_ + c];

    // load 3 padded rows (contiguous) into smem
    {
        const ulonglong2* src = (const ulonglong2*)(Xp + (((size_t)n * PH_ + oy) * PW_) * NW_);
        ulonglong2* dst = (ulonglong2*)sx;
        #pragma unroll
        for (int i = c; i < 3 * PW_ * NW_ / 2; i += 256) dst[i] = src[i];
    }
    __syncthreads();

    for (int ox = 0; ox < W_; ox += 2) {
        int acc0 = 0, acc1 = 0;
        #pragma unroll
        for (int ky = 0; ky < 3; ++ky) {
            #pragma unroll
            for (int col = 0; col < 4; ++col) {
                const ulonglong2* xp2 = (const ulonglong2*)&sx[((ky * PW_) + ox + col) * NW_];
                ulonglong2 xv0 = xp2[0], xv1 = xp2[1];
                if (col < 3) {
                    const int t = ky * 3 + col;
                    acc0 += __popcll(xv0.x ^ w[t][0]) + __popcll(xv0.y ^ w[t][1])
                          + __popcll(xv1.x ^ w[t][2]) + __popcll(xv1.y ^ w[t][3]);
                }
                if (col >= 1) {
                    const int t = ky * 3 + (col - 1);
                    acc1 += __popcll(xv0.x ^ w[t][0]) + __popcll(xv0.y ^ w[t][1])
                          + __popcll(xv1.x ^ w[t][2]) + __popcll(xv1.y ^ w[t][3]);
                }
            }
        }
        int s0 = 2304 - 2 * acc0 - ((ox == 0) ? cL : cM);
        int s1 = 2304 - 2 * acc1 - ((ox + 1 == W_ - 1) ? cR : cM);
        size_t pb = (((size_t)n * H_ + oy) * W_ + ox) * C_ + c;
        S[pb]      = (short)s0;
        S[pb + C_] = (short)s1;
    }
}

// ============================ stats / bn / thresh / final ============================
__global__ void stats_k(const short* __restrict__ S,
                        ull* __restrict__ sum, ull* __restrict__ sq) {
    int c = threadIdx.x, oy = blockIdx.x, n = blockIdx.y;
    const short* base = S + (((size_t)n * H_ + oy) * W_) * C_ + c;
    int s = 0, q = 0;
    for (int ox = 0; ox < W_; ++ox) {
        int v = base[(size_t)ox * C_];
        s += v; q += v * v;
    }
    atomicAdd(&sum[c], (ull)(long long)s);
    atomicAdd(&sq[c],  (ull)(long long)q);
}

__global__ void bnparams_k(const ull* __restrict__ sum, const ull* __restrict__ sq,
                           const float* __restrict__ gamma, const float* __restrict__ beta,
                           float* __restrict__ a, float* __restrict__ b) {
    int c = threadIdx.x;
    const double M = (double)M_CNT_;
    double mS = (double)(long long)sum[c] / M;
    double vS = (double)(long long)sq[c] / M - mS * mS;
    double m = 0.5 * mS;            // y = 0.5 * S
    double v = 0.25 * vS;
    double r = 1.0 / sqrt(v + 1e-5);
    double g = (double)gamma[c];
    a[c] = (float)(0.5 * r * g);
    b[c] = (float)((double)beta[c] - m * r * g);
}

// threshold conv1 sums -> packed padded bitplanes via warp ballot
__global__ void thresh_ballot_k(const short* __restrict__ S,
                                const float* __restrict__ a, const float* __restrict__ b,
                                u64* __restrict__ Xp2) {
    int c = threadIdx.x;            // 0..255
    int py = blockIdx.x, n = blockIdx.y;
    int warp = c >> 5, lane = c & 31;
    float av = a[c], bv = b[c];
    bool rowv = (py >= 1 && py <= H_);
    for (int px = 0; px < PW_; ++px) {
        unsigned bit = 0u;
        if (rowv && px >= 1 && px <= W_) {
            int v = S[(((size_t)n * H_ + (py - 1)) * W_ + (px - 1)) * C_ + c];
            bit = (av * (float)v + bv > 0.0f) ? 1u : 0u;
        }
        unsigned m = __ballot_sync(0xffffffffu, bit);
        if (lane == 0)
            ((unsigned*)(Xp2 + (((size_t)n * PH_ + py) * PW_ + px) * NW_))[warp] = m;
    }
}

// final: out = clip(a2*S2 + b2 + x, -1, 1), smem transpose (3136 = 98*32 exactly)
__global__ __launch_bounds__(256)
void final_k(const short* __restrict__ S2,
             const float* __restrict__ a, const float* __restrict__ b,
             const float* __restrict__ x, float* __restrict__ out) {
    __shared__ short tile[32][33];
    int n = blockIdx.z, pt = blockIdx.x, ct = blockIdx.y;
    int tx = threadIdx.x, ty = threadIdx.y;      // (32, 8)
    #pragma unroll
    for (int i = 0; i < 4; ++i) {
        int rl = ty + i * 8;
        tile[rl][tx] = S2[((size_t)n * PIX_ + pt * 32 + rl) * C_ + ct * 32 + tx];
    }
    __syncthreads();
    int p = pt * 32 + tx;
    int py = p / W_, px = p % W_;
    #pragma unroll
    for (int i = 0; i < 4; ++i) {
        int cl = ty + i * 8;
        int cc = ct * 32 + cl;
        size_t oi = (((size_t)n * C_ + cc) * H_ + py) * W_ + px;
        float v = a[cc] * (float)tile[tx][cl] + b[cc] + x[oi];
        out[oi] = fminf(1.0f, fmaxf(-1.0f, v));
    }
}

// ============================ launch ============================
extern "C" void kernel_launch(void* const* d_in, const int* in_sizes, int n_in,
                              void* d_out, int out_size) {
    const float* x  = (const float*)d_in[0];
    const float* w1 = (const float*)d_in[1];
    const float* g1 = (const float*)d_in[2];
    const float* b1 = (const float*)d_in[3];
    const float* w2 = (const float*)d_in[4];
    const float* g2 = (const float*)d_in[5];
    const float* b2 = (const float*)d_in[6];
    float* out = (float*)d_out;

    void *pX1, *pX2, *pW1, *pW2, *pc1, *pc2, *pS1, *pS2;
    void *psum1, *psq1, *psum2, *psq2, *pa1, *pb1, *pa2, *pb2;
    cudaGetSymbolAddress(&pX1, g_Xp1);  cudaGetSymbolAddress(&pX2, g_Xp2);
    cudaGetSymbolAddress(&pW1, g_Wp1);  cudaGetSymbolAddress(&pW2, g_Wp2);
    cudaGetSymbolAddress(&pc1, g_c1);   cudaGetSymbolAddress(&pc2, g_c2);
    cudaGetSymbolAddress(&pS1, g_S1);   cudaGetSymbolAddress(&pS2, g_S2);
    cudaGetSymbolAddress(&psum1, g_sum1); cudaGetSymbolAddress(&psq1, g_sq1);
    cudaGetSymbolAddress(&psum2, g_sum2); cudaGetSymbolAddress(&psq2, g_sq2);
    cudaGetSymbolAddress(&pa1, g_a1);   cudaGetSymbolAddress(&pb1, g_b1);
    cudaGetSymbolAddress(&pa2, g_a2);   cudaGetSymbolAddress(&pb2, g_b2);

    // setup (cheap)
    pack_w_k<<<9, 256>>>(w1, (u64*)pW1);
    pack_w_k<<<9, 256>>>(w2, (u64*)pW2);
    corr_w_k<<<1, 256>>>((const u64*)pW1, (int*)pc1);
    corr_w_k<<<1, 256>>>((const u64*)pW2, (int*)pc2);
    zero_stats_k<<<1, 256>>>();
    pack_x_k<<<dim3(PH_, N_), dim3(PW_, NW_)>>>(x, (u64*)pX1);

    // conv1
    conv_pop_k<<<dim3(H_, N_), 256>>>((const u64*)pX1, (const u64*)pW1,
                                      (const int*)pc1, (short*)pS1);
    stats_k<<<dim3(H_, N_), 256>>>((const short*)pS1, (ull*)psum1, (ull*)psq1);
    bnparams_k<<<1, 256>>>((const ull*)psum1, (const ull*)psq1, g1, b1,
                           (float*)pa1, (float*)pb1);
    thresh_ballot_k<<<dim3(PH_, N_), 256>>>((const short*)pS1,
        (const float*)pa1, (const float*)pb1, (u64*)pX2);

    // conv2
    conv_pop_k<<<dim3(H_, N_), 256>>>((const u64*)pX2, (const u64*)pW2,
                                      (const int*)pc2, (short*)pS2);
    stats_k<<<dim3(H_, N_), 256>>>((const short*)pS2, (ull*)psum2, (ull*)psq2);
    bnparams_k<<<1, 256>>>((const ull*)psum2, (const ull*)psq2, g2, b2,
                           (float*)pa2, (float*)pb2);

    final_k<<<dim3(PIX_ / 32, 8, N_), dim3(32, 8)>>>(
        (const short*)pS2, (const float*)pa2, (const float*)pb2, x, out);
}

// round 6
// speedup vs baseline: 2.3512x; 1.0436x over previous
#include <cuda_runtime.h>
#include <cstdint>

typedef unsigned long long u64;
typedef unsigned long long ull;

// ============================ problem constants ============================
#define N_   32
#define C_   256
#define H_   56
#define W_   56
#define PH_  58
#define PW_  58
#define PIX_ (H_*W_)                 // 3136
#define M_CNT_ (N_*PIX_)             // 100352
#define NW_  4                       // u64 words per pixel (256 ch)

// ============================ device scratch ============================
__device__ __align__(16) u64 g_Xp1[(size_t)N_*PH_*PW_*NW_];   // packed padded input (3.44 MB)
__device__ __align__(16) u64 g_Xp2[(size_t)N_*PH_*PW_*NW_];   // packed padded act2
__device__ __align__(16) u64 g_Wp1[9*C_*NW_];
__device__ __align__(16) u64 g_Wp2[9*C_*NW_];
__device__ int  g_c1[9*C_];
__device__ int  g_c2[9*C_];
__device__ __align__(16) short g_S1[(size_t)M_CNT_*C_];       // [pixel][cout] (51.4 MB)
__device__ __align__(16) short g_S2[(size_t)M_CNT_*C_];
__device__ ull g_sum1[C_], g_sq1[C_], g_sum2[C_], g_sq2[C_];
__device__ float g_a1[C_], g_b1[C_], g_a2[C_], g_b2[C_];

// ============================ setup kernels ============================
__global__ void zero_stats_k() {
    int i = threadIdx.x;
    g_sum1[i] = 0ull; g_sq1[i] = 0ull; g_sum2[i] = 0ull; g_sq2[i] = 0ull;
}

// pack weights: w [O=256][I=256][3][3] f32 -> Wp[t][cout][4] u64 (bit=1 means +1)
__global__ void pack_w_k(const float* __restrict__ w, u64* __restrict__ Wp) {
    int t = blockIdx.x;          // 0..8
    int c = threadIdx.x;         // cout
    int ky = t / 3, kx = t % 3;
    #pragma unroll
    for (int j = 0; j < NW_; ++j) {
        u64 bits = 0ull;
        #pragma unroll 4
        for (int cl = 0; cl < 64; ++cl) {
            int cin = j * 64 + cl;
            float v = w[(((size_t)c * C_ + cin) * 3 + ky) * 3 + kx];
            bits |= (u64)(v > 0.0f) << cl;
        }
        Wp[((size_t)t * C_ + c) * NW_ + j] = bits;
    }
}

// border corrections: corr[type][c] = sum over invalid taps of (256 - 2*popc(w_tap))
__global__ void corr_w_k(const u64* __restrict__ Wp, int* __restrict__ corr) {
    int c = threadIdx.x;
    int pc[9];
    #pragma unroll
    for (int t = 0; t < 9; ++t) {
        int s = 0;
        #pragma unroll
        for (int j = 0; j < NW_; ++j) s += __popcll(Wp[((size_t)t * C_ + c) * NW_ + j]);
        pc[t] = s;
    }
    for (int type = 0; type < 9; ++type) {
        int rt = type / 3, ct = type % 3;
        int s = 0;
        #pragma unroll
        for (int ky = 0; ky < 3; ++ky)
            #pragma unroll
            for (int kx = 0; kx < 3; ++kx) {
                bool rinv = (rt == 0 && ky == 0) || (rt == 2 && ky == 2);
                bool cinv = (ct == 0 && kx == 0) || (ct == 2 && kx == 2);
                if (rinv || cinv) s += 256 - 2 * pc[ky * 3 + kx];
            }
        corr[type * C_ + c] = s;
    }
}

// binarize x (NCHW f32) -> padded packed bitplanes, halo = 0 bits
__global__ void pack_x_k(const float* __restrict__ x, u64* __restrict__ Xp) {
    int px = threadIdx.x;   // 0..57
    int j  = threadIdx.y;   // 0..3
    int py = blockIdx.x;    // 0..57
    int n  = blockIdx.y;
    size_t oidx = (((size_t)n * PH_ + py) * PW_ + px) * NW_ + j;
    if (px == 0 || px == PW_ - 1 || py == 0 || py == PH_ - 1) { Xp[oidx] = 0ull; return; }
    const float* xp = x + (((size_t)n * C_ + j * 64) * H_ + (py - 1)) * W_ + (px - 1);
    u64 bits = 0ull;
    #pragma unroll 8
    for (int cl = 0; cl < 64; ++cl)
        bits |= (u64)(xp[(size_t)cl * PIX_] > 0.0f) << cl;
    Xp[oidx] = bits;
}

// ============================ hot kernel: XNOR-popcount conv (split-half) ============================
// thread = (cout, half): 128 channels x 2 halves per CTA; grid.z = 2 channel groups.
// Weights (18 u64) in regs; x rows broadcast from smem; partner merge via shfl_xor(1).
// BN stats fused into the epilogue.
__global__ __launch_bounds__(256, 4)
void conv_pop_k(const u64* __restrict__ Xp,
                const u64* __restrict__ Wp,
                const int* __restrict__ corr,
                short* __restrict__ S,
                ull* __restrict__ sum, ull* __restrict__ sq)
{
    __shared__ u64 sx[3 * PW_ * NW_];     // 696 u64 = 5568 B
    const int t    = threadIdx.x;
    const int half = t & 1;
    const int c    = blockIdx.z * 128 + (t >> 1);
    const int oy   = blockIdx.x;
    const int n    = blockIdx.y;

    // this thread's half of the weights: 9 taps x 2 u64
    u64 w[9][2];
    #pragma unroll
    for (int tp = 0; tp < 9; ++tp) {
        const ulonglong2 v = *(const ulonglong2*)&Wp[((size_t)tp * C_ + c) * NW_ + half * 2];
        w[tp][0] = v.x; w[tp][1] = v.y;
    }
    const int rt = (oy == 0) ? 0 : ((oy == H_ - 1) ? 2 : 1);
    const int cL = corr[(rt * 3 + 0) * C_ + c];
    const int cM = corr[(rt * 3 + 1) * C_ + c];
    const int cR = corr[(rt * 3 + 2) * C_ + c];

    // load 3 padded rows (contiguous) into smem: 348 ulonglong2 by 256 threads
    {
        const ulonglong2* src = (const ulonglong2*)(Xp + (((size_t)n * PH_ + oy) * PW_) * NW_);
        ulonglong2* dst = (ulonglong2*)sx;
        for (int i = t; i < 3 * PW_ * NW_ / 2; i += 256) dst[i] = src[i];
    }
    __syncthreads();

    int ss = 0, qq = 0;
    const size_t rowbase = (((size_t)n * H_ + oy) * W_) * C_ + c;

    #pragma unroll 1
    for (int ox = 0; ox < W_; ox += 2) {
        int a0 = 0, a1 = 0;
        #pragma unroll
        for (int ky = 0; ky < 3; ++ky) {
            #pragma unroll
            for (int col = 0; col < 4; ++col) {
                const ulonglong2 xv =
                    *(const ulonglong2*)&sx[((ky * PW_) + ox + col) * NW_ + half * 2];
                if (col < 3) {
                    const int tp = ky * 3 + col;
                    a0 += __popcll(xv.x ^ w[tp][0]) + __popcll(xv.y ^ w[tp][1]);
                }
                if (col >= 1) {
                    const int tp = ky * 3 + (col - 1);
                    a1 += __popcll(xv.x ^ w[tp][0]) + __popcll(xv.y ^ w[tp][1]);
                }
            }
        }
        const int f0 = a0 + __shfl_xor_sync(0xffffffffu, a0, 1);
        const int f1 = a1 + __shfl_xor_sync(0xffffffffu, a1, 1);
        if (!half) {
            int s0 = 2304 - 2 * f0 - ((ox == 0) ? cL : cM);
            int s1 = 2304 - 2 * f1 - ((ox + 1 == W_ - 1) ? cR : cM);
            S[rowbase + (size_t)ox * C_]       = (short)s0;
            S[rowbase + (size_t)(ox + 1) * C_] = (short)s1;
            ss += s0 + s1;
            qq += s0 * s0 + s1 * s1;
        }
    }
    if (!half) {
        atomicAdd(&sum[c], (ull)(long long)ss);
        atomicAdd(&sq[c],  (ull)(long long)qq);
    }
}

// ============================ bn / thresh / final ============================
__global__ void bnparams_k(const ull* __restrict__ sum, const ull* __restrict__ sq,
                           const float* __restrict__ gamma, const float* __restrict__ beta,
                           float* __restrict__ a, float* __restrict__ b) {
    int c = threadIdx.x;
    const double M = (double)M_CNT_;
    double mS = (double)(long long)sum[c] / M;
    double vS = (double)(long long)sq[c] / M - mS * mS;
    double m = 0.5 * mS;            // y = 0.5 * S
    double v = 0.25 * vS;
    double r = 1.0 / sqrt(v + 1e-5);
    double g = (double)gamma[c];
    a[c] = (float)(0.5 * r * g);
    b[c] = (float)((double)beta[c] - m * r * g);
}

// threshold conv1 sums -> packed padded bitplanes via warp ballot
__global__ void thresh_ballot_k(const short* __restrict__ S,
                                const float* __restrict__ a, const float* __restrict__ b,
                                u64* __restrict__ Xp2) {
    int c = threadIdx.x;            // 0..255
    int py = blockIdx.x, n = blockIdx.y;
    int warp = c >> 5, lane = c & 31;
    float av = a[c], bv = b[c];
    bool rowv = (py >= 1 && py <= H_);
    for (int px = 0; px < PW_; ++px) {
        unsigned bit = 0u;
        if (rowv && px >= 1 && px <= W_) {
            int v = S[(((size_t)n * H_ + (py - 1)) * W_ + (px - 1)) * C_ + c];
            bit = (av * (float)v + bv > 0.0f) ? 1u : 0u;
        }
        unsigned m = __ballot_sync(0xffffffffu, bit);
        if (lane == 0)
            ((unsigned*)(Xp2 + (((size_t)n * PH_ + py) * PW_ + px) * NW_))[warp] = m;
    }
}

// final: out = clip(a2*S2 + b2 + x, -1, 1), smem transpose (3136 = 98*32)
__global__ __launch_bounds__(256)
void final_k(const short* __restrict__ S2,
             const float* __restrict__ a, const float* __restrict__ b,
             const float* __restrict__ x, float* __restrict__ out) {
    __shared__ short tile[32][33];
    int n = blockIdx.z, pt = blockIdx.x, ct = blockIdx.y;
    int tx = threadIdx.x, ty = threadIdx.y;      // (32, 8)
    #pragma unroll
    for (int i = 0; i < 4; ++i) {
        int rl = ty + i * 8;
        tile[rl][tx] = S2[((size_t)n * PIX_ + pt * 32 + rl) * C_ + ct * 32 + tx];
    }
    __syncthreads();
    int p = pt * 32 + tx;
    int py = p / W_, px = p % W_;
    #pragma unroll
    for (int i = 0; i < 4; ++i) {
        int cl = ty + i * 8;
        int cc = ct * 32 + cl;
        size_t oi = (((size_t)n * C_ + cc) * H_ + py) * W_ + px;
        float v = a[cc] * (float)tile[tx][cl] + b[cc] + x[oi];
        out[oi] = fminf(1.0f, fmaxf(-1.0f, v));
    }
}

// ============================ launch ============================
extern "C" void kernel_launch(void* const* d_in, const int* in_sizes, int n_in,
                              void* d_out, int out_size) {
    const float* x  = (const float*)d_in[0];
    const float* w1 = (const float*)d_in[1];
    const float* g1 = (const float*)d_in[2];
    const float* b1 = (const float*)d_in[3];
    const float* w2 = (const float*)d_in[4];
    const float* g2 = (const float*)d_in[5];
    const float* b2 = (const float*)d_in[6];
    float* out = (float*)d_out;

    void *pX1, *pX2, *pW1, *pW2, *pc1, *pc2, *pS1, *pS2;
    void *psum1, *psq1, *psum2, *psq2, *pa1, *pb1, *pa2, *pb2;
    cudaGetSymbolAddress(&pX1, g_Xp1);  cudaGetSymbolAddress(&pX2, g_Xp2);
    cudaGetSymbolAddress(&pW1, g_Wp1);  cudaGetSymbolAddress(&pW2, g_Wp2);
    cudaGetSymbolAddress(&pc1, g_c1);   cudaGetSymbolAddress(&pc2, g_c2);
    cudaGetSymbolAddress(&pS1, g_S1);   cudaGetSymbolAddress(&pS2, g_S2);
    cudaGetSymbolAddress(&psum1, g_sum1); cudaGetSymbolAddress(&psq1, g_sq1);
    cudaGetSymbolAddress(&psum2, g_sum2); cudaGetSymbolAddress(&psq2, g_sq2);
    cudaGetSymbolAddress(&pa1, g_a1);   cudaGetSymbolAddress(&pb1, g_b1);
    cudaGetSymbolAddress(&pa2, g_a2);   cudaGetSymbolAddress(&pb2, g_b2);

    // setup (cheap)
    pack_w_k<<<9, 256>>>(w1, (u64*)pW1);
    pack_w_k<<<9, 256>>>(w2, (u64*)pW2);
    corr_w_k<<<1, 256>>>((const u64*)pW1, (int*)pc1);
    corr_w_k<<<1, 256>>>((const u64*)pW2, (int*)pc2);
    zero_stats_k<<<1, 256>>>();
    pack_x_k<<<dim3(PH_, N_), dim3(PW_, NW_)>>>(x, (u64*)pX1);

    // conv1 (+fused stats)
    conv_pop_k<<<dim3(H_, N_, 2), 256>>>((const u64*)pX1, (const u64*)pW1,
                                         (const int*)pc1, (short*)pS1,
                                         (ull*)psum1, (ull*)psq1);
    bnparams_k<<<1, 256>>>((const ull*)psum1, (const ull*)psq1, g1, b1,
                           (float*)pa1, (float*)pb1);
    thresh_ballot_k<<<dim3(PH_, N_), 256>>>((const short*)pS1,
        (const float*)pa1, (const float*)pb1, (u64*)pX2);

    // conv2 (+fused stats)
    conv_pop_k<<<dim3(H_, N_, 2), 256>>>((const u64*)pX2, (const u64*)pW2,
                                         (const int*)pc2, (short*)pS2,
                                         (ull*)psum2, (ull*)psq2);
    bnparams_k<<<1, 256>>>((const ull*)psum2, (const ull*)psq2, g2, b2,
                           (float*)pa2, (float*)pb2);

    final_k<<<dim3(PIX_ / 32, 8, N_), dim3(32, 8)>>>(
        (const short*)pS2, (const float*)pa2, (const float*)pb2, x, out);
}